// round 16
// baseline (speedup 1.0000x reference)
#include <cuda_runtime.h>
#include <cstdint>

#define N_ROWS   16384
#define D        1024
#define D4       (D / 4)          // 256 float4 per row
#define TEMPC    0.05f
#define EPSC     1e-8f

#define THREADS     256
#define WARPS_CTA   8
#define GRID        (N_ROWS / WARPS_CTA)   // 2048 CTAs, exactly 1 row per warp
#define F4_PER_LANE (D4 / 32)              // 8

#define FP_SCALE    1073741824.0f          // 2^30 fixed-point (loss >= 0)
#define CNT_ONE     (1ULL << 52)           // completion count in high bits
#define SUM_MASK    (CNT_ONE - 1ULL)

// Global accumulator: low 52 bits fixed-point sum, bits >=52 CTA count.
// Integer adds are exact+commutative -> deterministic for any arrival order.
__device__ unsigned long long g_acc = 0ULL;

__global__ __launch_bounds__(THREADS) void byol_v16_kernel(
    const float4* __restrict__ a4, const float4* __restrict__ b4,
    float* __restrict__ out)
{
    const int t   = threadIdx.x;
    const int wid = t >> 5;
    const int lid = t & 31;

    const int  row = blockIdx.x * WARPS_CTA + wid;
    const long idx = (long)row * D4 + lid;

    // 16 front-batched interleaved LDG.128 (R14 schedule, unchanged)
    float4 av[F4_PER_LANE], bv[F4_PER_LANE];
    #pragma unroll
    for (int j = 0; j < F4_PER_LANE; j++) {
        av[j] = a4[idx + 32 * j];
        bv[j] = b4[idx + 32 * j];
    }

    float dot = 0.f, aa = 0.f, bb = 0.f;
    #pragma unroll
    for (int j = 0; j < F4_PER_LANE; j++) {
        dot += av[j].x * bv[j].x + av[j].y * bv[j].y
             + av[j].z * bv[j].z + av[j].w * bv[j].w;
        aa  += av[j].x * av[j].x + av[j].y * av[j].y
             + av[j].z * av[j].z + av[j].w * av[j].w;
        bb  += bv[j].x * bv[j].x + bv[j].y * bv[j].y
             + bv[j].z * bv[j].z + bv[j].w * bv[j].w;
    }

    #pragma unroll
    for (int off = 16; off > 0; off >>= 1) {
        dot += __shfl_xor_sync(0xffffffffu, dot, off);
        aa  += __shfl_xor_sync(0xffffffffu, aa,  off);
        bb  += __shfl_xor_sync(0xffffffffu, bb,  off);
    }

    // Per-warp loss into smem (fixed slot per warp)
    __shared__ float s_warp[WARPS_CTA];
    if (lid == 0) {
        const float n1 = fmaxf(sqrtf(aa), EPSC);
        const float n2 = fmaxf(sqrtf(bb), EPSC);
        s_warp[wid] = 2.0f - 2.0f * (dot / (n1 * n2));
    }
    __syncthreads();

    // Warp 0: parallel combine (1 LDS wavefront + 3 shfl, fixed tree order)
    if (wid == 0) {
        float p = (lid < WARPS_CTA) ? s_warp[lid] : 0.f;
        p += __shfl_down_sync(0xffffffffu, p, 4);
        p += __shfl_down_sync(0xffffffffu, p, 2);
        p += __shfl_down_sync(0xffffffffu, p, 1);

        if (lid == 0) {
            // Fixed-point contribution + completion count, one atomic total
            const unsigned long long contrib =
                (unsigned long long)llrintf(p * FP_SCALE) + CNT_ONE;
            const unsigned long long old = atomicAdd(&g_acc, contrib);

            if ((old >> 52) == (unsigned long long)(GRID - 1)) {
                const unsigned long long total = (old + contrib) & SUM_MASK;
                out[0] = ((float)((double)total / (double)FP_SCALE))
                         / ((float)N_ROWS * TEMPC);
                g_acc = 0ULL;   // reset for graph replay
            }
        }
    }
}

extern "C" void kernel_launch(void* const* d_in, const int* in_sizes, int n_in,
                              void* d_out, int out_size)
{
    const float4* a4 = (const float4*)d_in[0];  // online_output [16384,1024] f32
    const float4* b4 = (const float4*)d_in[1];  // target_output [16384,1024] f32
    float* out = (float*)d_out;

    byol_v16_kernel<<<GRID, THREADS>>>(a4, b4, out);
}

// round 17
// speedup vs baseline: 1.1671x; 1.1671x over previous
#include <cuda_runtime.h>
#include <cstdint>

#define N_ROWS   16384
#define D        1024
#define D4       (D / 4)          // 256 float4 per row
#define TEMPC    0.05f
#define EPSC     1e-8f

#define THREADS     256
#define WARPS_CTA   8
#define GRID        (N_ROWS / WARPS_CTA)   // 2048 CTAs, exactly 1 row per warp
#define F4_PER_LANE (D4 / 32)              // 8

#define FP_SCALE    1073741824.0f          // 2^30 fixed-point
#define CNT_ONE     (1ULL << 52)           // completion count in high bits
#define SUM_MASK    (CNT_ONE - 1ULL)

// Single accumulator: low 52 bits fixed-point sum, bits >=52 CTA count.
// Integer adds are exact+commutative -> deterministic for any arrival order.
__device__ unsigned long long g_acc = 0ULL;

__global__ __launch_bounds__(THREADS) void byol_v14_kernel(
    const float4* __restrict__ a4, const float4* __restrict__ b4,
    float* __restrict__ out)
{
    const int t   = threadIdx.x;
    const int wid = t >> 5;
    const int lid = t & 31;

    const int  row = blockIdx.x * WARPS_CTA + wid;
    const long idx = (long)row * D4 + lid;

    // 16 front-batched interleaved LDG.128: both streams in flight at once
    float4 av[F4_PER_LANE], bv[F4_PER_LANE];
    #pragma unroll
    for (int j = 0; j < F4_PER_LANE; j++) {
        av[j] = a4[idx + 32 * j];
        bv[j] = b4[idx + 32 * j];
    }

    float dot = 0.f, aa = 0.f, bb = 0.f;
    #pragma unroll
    for (int j = 0; j < F4_PER_LANE; j++) {
        dot += av[j].x * bv[j].x + av[j].y * bv[j].y
             + av[j].z * bv[j].z + av[j].w * bv[j].w;
        aa  += av[j].x * av[j].x + av[j].y * av[j].y
             + av[j].z * av[j].z + av[j].w * av[j].w;
        bb  += bv[j].x * bv[j].x + bv[j].y * bv[j].y
             + bv[j].z * bv[j].z + bv[j].w * bv[j].w;
    }

    #pragma unroll
    for (int off = 16; off > 0; off >>= 1) {
        dot += __shfl_xor_sync(0xffffffffu, dot, off);
        aa  += __shfl_xor_sync(0xffffffffu, aa,  off);
        bb  += __shfl_xor_sync(0xffffffffu, bb,  off);
    }

    // CTA combine (fixed warp order -> deterministic contribution value)
    __shared__ float s_warp[WARPS_CTA];
    if (lid == 0) {
        const float n1 = fmaxf(sqrtf(aa), EPSC);
        const float n2 = fmaxf(sqrtf(bb), EPSC);
        s_warp[wid] = 2.0f - 2.0f * (dot / (n1 * n2));
    }
    __syncthreads();

    if (t == 0) {
        float p = 0.f;
        #pragma unroll
        for (int w = 0; w < WARPS_CTA; w++) p += s_warp[w];

        // Fixed-point contribution + completion count, one atomic total
        const unsigned long long contrib =
            (unsigned long long)llrintf(p * FP_SCALE) + CNT_ONE;
        const unsigned long long old = atomicAdd(&g_acc, contrib);

        if ((old >> 52) == (unsigned long long)(GRID - 1)) {
            // This CTA completes the sum: old + contrib is the grand total
            const unsigned long long total = (old + contrib) & SUM_MASK;
            out[0] = ((float)((double)total / (double)FP_SCALE))
                     / ((float)N_ROWS * TEMPC);
            g_acc = 0ULL;   // reset for graph replay (only reader/writer now)
        }
    }
}

extern "C" void kernel_launch(void* const* d_in, const int* in_sizes, int n_in,
                              void* d_out, int out_size)
{
    const float4* a4 = (const float4*)d_in[0];  // online_output [16384,1024] f32
    const float4* b4 = (const float4*)d_in[1];  // target_output [16384,1024] f32
    float* out = (float*)d_out;

    byol_v14_kernel<<<GRID, THREADS>>>(a4, b4, out);
}